// round 15
// baseline (speedup 1.0000x reference)
#include <cuda_runtime.h>
#include <cuda_fp16.h>
#include <cstdint>

// Problem constants (fixed by reference setup_inputs)
#define BATCH 16
#define CIN   128
#define COUT  128
#define HH    128
#define WW    128
#define SS    512
#define EPS   1e-8f
#define HW    (HH * WW)

#define NCHUNKS 36                 // 9 (kh,kw) x 4 ci-blocks of 32
#define A_BYTES 8192               // 128co x 32k fp16, fragment-major
#define B_FRAG_STRIDE 272          // 32 lanes x 8B + 16B pad
#define B_BYTES (32 * B_FRAG_STRIDE)   // 8704
#define B_OFF   (2 * A_BYTES)
#define SMEM_TOTAL (2 * A_BYTES + 2 * B_BYTES)   // 33792

// Scratch (allocation-free)
__device__ float g_s[BATCH * CIN];
__device__ float g_wsq[COUT * CIN];
__device__ float g_decoef[BATCH * COUT];
// modulated fp16x2 weights, m16n8k16-fragment-major:
// [b][khkw(9)][cic(4)] x [k16(2)][mfrag(8)][lane(32)][reg(4)] u32
__device__ __align__(16) uint32_t g_wmod[BATCH * 9 * 4 * 2048];  // 4.7 MB

// ---------------------------------------------------------------------------
__device__ __forceinline__ uint32_t smem_u32(const void* p) {
    return (uint32_t)__cvta_generic_to_shared(p);
}
__device__ __forceinline__ void cp16(uint32_t dst, const void* src) {
    asm volatile("cp.async.cg.shared.global [%0], [%1], 16;"
                 :: "r"(dst), "l"(src) : "memory");
}
__device__ __forceinline__ uint32_t packh2(float lo, float hi) {
    __half2 h = __floats2half2_rn(lo, hi);
    return *reinterpret_cast<uint32_t*>(&h);
}
__device__ __forceinline__ void mma16(float* d, const uint32_t* a, const uint32_t* b) {
    asm volatile(
        "mma.sync.aligned.m16n8k16.row.col.f32.f16.f16.f32 "
        "{%0,%1,%2,%3}, {%4,%5,%6,%7}, {%8,%9}, {%0,%1,%2,%3};"
        : "+f"(d[0]), "+f"(d[1]), "+f"(d[2]), "+f"(d[3])
        : "r"(a[0]), "r"(a[1]), "r"(a[2]), "r"(a[3]), "r"(b[0]), "r"(b[1]));
}

// ---------------------------------------------------------------------------
__global__ void k_modscale(const float* __restrict__ style,
                           const float* __restrict__ mod_w,
                           const float* __restrict__ mod_b) {
    int t = blockIdx.x * blockDim.x + threadIdx.x;
    if (t >= BATCH * CIN) return;
    int b = t >> 7, ci = t & 127;
    const float* st = style + b * SS;
    const float* mw = mod_w + ci * SS;
    float acc = 0.f;
#pragma unroll 8
    for (int j = 0; j < SS; ++j) acc = fmaf(st[j], mw[j], acc);
    g_s[t] = acc + mod_b[ci];
}

__global__ void k_wsq(const float* __restrict__ weight) {
    int t = blockIdx.x * blockDim.x + threadIdx.x;
    if (t >= COUT * CIN) return;
    const float* w = weight + t * 9;
    float acc = 0.f;
#pragma unroll
    for (int k = 0; k < 9; ++k) acc = fmaf(w[k], w[k], acc);
    g_wsq[t] = acc;
}

__global__ void k_decoef() {
    int t = blockIdx.x * blockDim.x + threadIdx.x;
    if (t >= BATCH * COUT) return;
    int b = t >> 7, co = t & 127;
    const float* sv = g_s + b * CIN;
    const float* wq = g_wsq + co * CIN;
    float acc = 0.f;
#pragma unroll 8
    for (int ci = 0; ci < CIN; ++ci) {
        float s = sv[ci];
        acc = fmaf(wq[ci], s * s, acc);
    }
    g_decoef[t] = rsqrtf(acc + EPS);
}

// A fragment (m16n8k16 f16, row-major A): lane l -> r=l>>2, c=l&3.
// reg e0: A[r][2c..2c+1], e1: A[r+8][2c..], e2: A[r][2c+8..], e3: A[r+8][2c+8..]
__global__ void k_wmod(const float* __restrict__ weight) {
    int t = blockIdx.x * blockDim.x + threadIdx.x;
    if (t >= BATCH * 9 * 4 * 2048) return;
    int e    = t & 3;
    int lane = (t >> 2) & 31;
    int mf   = (t >> 7) & 7;
    int k16  = (t >> 10) & 1;
    int cic  = (t >> 11) & 3;
    int rest = t >> 13;
    int khkw = rest % 9;
    int b    = rest / 9;
    int r = lane >> 2, c = lane & 3;
    int co  = mf * 16 + r + (e & 1) * 8;
    int ci0 = cic * 32 + k16 * 16 + 2 * c + ((e >> 1) & 1) * 8;
    int kh = khkw / 3, kw = khkw % 3;
    float dc = g_decoef[b * COUT + co];
    float v0 = weight[((co * CIN + ci0) * 3 + kh) * 3 + kw]
               * g_s[b * CIN + ci0] * dc;
    float v1 = weight[((co * CIN + ci0 + 1) * 3 + kh) * 3 + kw]
               * g_s[b * CIN + ci0 + 1] * dc;
    g_wmod[t] = packh2(v0, v1);
}

// ---------------------------------------------------------------------------
// FP16 mma.sync implicit-GEMM conv, deep-pipelined B staging.
// CTA: (b, 128 co, 1 image row = 128 px). 256 threads = 8 warps (2m x 4n).
// Warp tile 64co x 32px; acc = 4x4 fragments x 4 fp32.
__global__ __launch_bounds__(256, 2)
void k_conv(const float* __restrict__ x, float* __restrict__ out) {
    extern __shared__ __align__(16) char smem_raw[];
    const uint32_t base = smem_u32(smem_raw);

    const int tid = threadIdx.x;
    const int wid = tid >> 5;
    const int lane = tid & 31;
    const int b  = blockIdx.y;
    const int y0 = blockIdx.x;
    const int mw = wid >> 2;            // 0..1
    const int nw = wid & 3;             // 0..3

    // B staging ids: thread = (px, hB); hB selects k16 block (ci 0-15 / 16-31)
    const int px = tid & 127;
    const int hB = tid >> 7;
    const int nf_s = px >> 3;
    const int laneb = (px & 7) * 4;

    float acc[4][4][4];
#pragma unroll
    for (int i = 0; i < 4; ++i)
#pragma unroll
        for (int j = 0; j < 4; ++j)
#pragma unroll
            for (int q = 0; q < 4; ++q) acc[i][j][q] = 0.f;

    float vb[2][16];                    // double-buffered LDG landing regs

    auto stageA = [&](int c) {
        const int s = c & 1;
        const uint32_t* asrc = g_wmod + ((size_t)b * 36 + c) * 2048;
        const uint32_t abase = base + s * A_BYTES;
#pragma unroll
        for (int it = 0; it < 2; ++it) {
            int i = tid + it * 256;        // 0..511, 16B each
            cp16(abase + i * 16, asrc + i * 4);
        }
        asm volatile("cp.async.commit_group;" ::: "memory");
    };
    auto ldgB = [&](int c, float* dst) {
        const int khkw = c >> 2, cic = c & 3;
        const int kh = khkw / 3, kw = khkw - kh * 3;
        const int gy = y0 + kh - 1;
        const int gx = px + kw - 1;
        const bool ok = ((unsigned)gy < HH) & ((unsigned)gx < WW);
        const float* p = x + (((size_t)b * CIN + cic * 32 + hB * 16) * HH + gy) * WW + gx;
#pragma unroll
        for (int j = 0; j < 16; ++j)
            dst[j] = ok ? __ldg(p + j * HW) : 0.f;
    };
    auto stsB = [&](int c) {
        const int s = c & 1;
        const float* v = vb[s];
        const uint32_t bbase = base + B_OFF + s * B_BYTES;
        const int fb = hB * 16 + nf_s;
#pragma unroll
        for (int q = 0; q < 4; ++q) {
            uint32_t b0 = packh2(v[2 * q], v[2 * q + 1]);
            uint32_t b1 = packh2(v[2 * q + 8], v[2 * q + 9]);
            uint32_t addr = bbase + fb * B_FRAG_STRIDE + (laneb + q) * 8;
            asm volatile("st.shared.v2.b32 [%0], {%1,%2};"
                         :: "r"(addr), "r"(b0), "r"(b1) : "memory");
        }
    };

    // prologue: chunk 0 staged fully; chunk 1's B loads in flight
    stageA(0);
    ldgB(0, vb[0]);
    stsB(0);
    ldgB(1, vb[1]);
    asm volatile("cp.async.wait_group 0;" ::: "memory");
    __syncthreads();

    for (int c = 0; c < NCHUNKS; ++c) {
        // off-tail staging: A(c+1) async; B(c+1) pack+STS (data from c-1);
        // B(c+2) LDG issue (lands during next chunk's MMAs)
        if (c + 1 < NCHUNKS) {
            stageA(c + 1);
            stsB(c + 1);
        }
        if (c + 2 < NCHUNKS) ldgB(c + 2, vb[c & 1]);

        // ---- MMA over chunk c (K=32 -> 2 k16 steps) ----
        const int s = c & 1;
        const uint32_t abase = base + s * A_BYTES;
        const uint32_t bbase = base + B_OFF + s * B_BYTES;
#pragma unroll
        for (int k16 = 0; k16 < 2; ++k16) {
            uint32_t av[4][4];
#pragma unroll
            for (int ai = 0; ai < 4; ++ai) {
                uint32_t addr = abase +
                    (((uint32_t)(k16 * 8 + mw * 4 + ai) * 32 + lane) << 4);
                asm volatile("ld.shared.v4.b32 {%0,%1,%2,%3}, [%4];"
                             : "=r"(av[ai][0]), "=r"(av[ai][1]),
                               "=r"(av[ai][2]), "=r"(av[ai][3])
                             : "r"(addr));
            }
            uint32_t bv[4][2];
#pragma unroll
            for (int fi = 0; fi < 4; ++fi) {
                int fb = k16 * 16 + nw * 4 + fi;
                uint32_t addr = bbase + fb * B_FRAG_STRIDE + lane * 8;
                asm volatile("ld.shared.v2.b32 {%0,%1}, [%2];"
                             : "=r"(bv[fi][0]), "=r"(bv[fi][1]) : "r"(addr));
            }
#pragma unroll
            for (int ai = 0; ai < 4; ++ai)
#pragma unroll
                for (int fi = 0; fi < 4; ++fi)
                    mma16(acc[ai][fi], av[ai], bv[fi]);
        }
        if (c + 1 < NCHUNKS)
            asm volatile("cp.async.wait_group 0;" ::: "memory");
        __syncthreads();
    }

    // ---- epilogue: D fragment row r = lane>>2, cols 2q (q=lane&3) ----
    const int r = lane >> 2, q = lane & 3;
#pragma unroll
    for (int ai = 0; ai < 4; ++ai) {
        int co0 = mw * 64 + ai * 16 + r;
#pragma unroll
        for (int fi = 0; fi < 4; ++fi) {
            int pxo = nw * 32 + fi * 8 + 2 * q;
            float* o0 = out + (((size_t)b * COUT + co0) * HH + y0) * WW + pxo;
            float* o1 = o0 + 8 * (size_t)HW;       // co0 + 8
            reinterpret_cast<float2*>(o0)[0] =
                make_float2(acc[ai][fi][0], acc[ai][fi][1]);
            reinterpret_cast<float2*>(o1)[0] =
                make_float2(acc[ai][fi][2], acc[ai][fi][3]);
        }
    }
}

// ---------------------------------------------------------------------------
extern "C" void kernel_launch(void* const* d_in, const int* in_sizes, int n_in,
                              void* d_out, int out_size) {
    const float* x      = (const float*)d_in[0];
    const float* style  = (const float*)d_in[1];
    const float* weight = (const float*)d_in[2];
    const float* mod_w  = (const float*)d_in[3];
    const float* mod_b  = (const float*)d_in[4];
    float* out = (float*)d_out;

    k_modscale<<<(BATCH * CIN + 255) / 256, 256>>>(style, mod_w, mod_b);
    k_wsq<<<(COUT * CIN + 255) / 256, 256>>>(weight);
    k_decoef<<<(BATCH * COUT + 255) / 256, 256>>>();
    k_wmod<<<(BATCH * 9 * 4 * 2048 + 255) / 256, 256>>>(weight);

    cudaFuncSetAttribute(k_conv, cudaFuncAttributeMaxDynamicSharedMemorySize,
                         SMEM_TOTAL);
    dim3 grid(HH, BATCH);
    k_conv<<<grid, 256, SMEM_TOTAL>>>(x, out);
}

// round 17
// speedup vs baseline: 1.2380x; 1.2380x over previous
#include <cuda_runtime.h>
#include <cuda_fp16.h>
#include <cstdint>

// Problem constants (fixed by reference setup_inputs)
#define BATCH 16
#define CIN   128
#define COUT  128
#define HH    128
#define WW    128
#define SS    512
#define EPS   1e-8f
#define HW    (HH * WW)

#define NCHUNKS 36                 // 9 (kh,kw) x 4 ci-blocks of 32
#define A_BYTES 8192               // 128co x 32k fp16, fragment-major
#define B_FRAG_STRIDE 272          // 32 lanes x 8B + 16B pad
#define B_BYTES (32 * B_FRAG_STRIDE)   // 8704
#define B_OFF   (2 * A_BYTES)
#define SMEM_TOTAL (2 * A_BYTES + 2 * B_BYTES)   // 33792

// Scratch (allocation-free)
__device__ float g_s[BATCH * CIN];
__device__ float g_wsq[COUT * CIN];
__device__ float g_decoef[BATCH * COUT];
// modulated fp16x2 weights, m16n8k16-fragment-major:
// [b][khkw(9)][cic(4)] x [k16(2)][mfrag(8)][lane(32)][reg(4)] u32
__device__ __align__(16) uint32_t g_wmod[BATCH * 9 * 4 * 2048];  // 4.7 MB

// ---------------------------------------------------------------------------
__device__ __forceinline__ uint32_t smem_u32(const void* p) {
    return (uint32_t)__cvta_generic_to_shared(p);
}
__device__ __forceinline__ void cp16(uint32_t dst, const void* src) {
    asm volatile("cp.async.cg.shared.global [%0], [%1], 16;"
                 :: "r"(dst), "l"(src) : "memory");
}
__device__ __forceinline__ uint32_t packh2(float lo, float hi) {
    __half2 h = __floats2half2_rn(lo, hi);
    return *reinterpret_cast<uint32_t*>(&h);
}
__device__ __forceinline__ void mma16(float* d, const uint32_t* a, const uint32_t* b) {
    asm volatile(
        "mma.sync.aligned.m16n8k16.row.col.f32.f16.f16.f32 "
        "{%0,%1,%2,%3}, {%4,%5,%6,%7}, {%8,%9}, {%0,%1,%2,%3};"
        : "+f"(d[0]), "+f"(d[1]), "+f"(d[2]), "+f"(d[3])
        : "r"(a[0]), "r"(a[1]), "r"(a[2]), "r"(a[3]), "r"(b[0]), "r"(b[1]));
}

// ---------------------------------------------------------------------------
__global__ void k_modscale(const float* __restrict__ style,
                           const float* __restrict__ mod_w,
                           const float* __restrict__ mod_b) {
    int t = blockIdx.x * blockDim.x + threadIdx.x;
    if (t >= BATCH * CIN) return;
    int b = t >> 7, ci = t & 127;
    const float* st = style + b * SS;
    const float* mw = mod_w + ci * SS;
    float acc = 0.f;
#pragma unroll 8
    for (int j = 0; j < SS; ++j) acc = fmaf(st[j], mw[j], acc);
    g_s[t] = acc + mod_b[ci];
}

__global__ void k_wsq(const float* __restrict__ weight) {
    int t = blockIdx.x * blockDim.x + threadIdx.x;
    if (t >= COUT * CIN) return;
    const float* w = weight + t * 9;
    float acc = 0.f;
#pragma unroll
    for (int k = 0; k < 9; ++k) acc = fmaf(w[k], w[k], acc);
    g_wsq[t] = acc;
}

__global__ void k_decoef() {
    int t = blockIdx.x * blockDim.x + threadIdx.x;
    if (t >= BATCH * COUT) return;
    int b = t >> 7, co = t & 127;
    const float* sv = g_s + b * CIN;
    const float* wq = g_wsq + co * CIN;
    float acc = 0.f;
#pragma unroll 8
    for (int ci = 0; ci < CIN; ++ci) {
        float s = sv[ci];
        acc = fmaf(wq[ci], s * s, acc);
    }
    g_decoef[t] = rsqrtf(acc + EPS);
}

// A fragment (m16n8k16 f16, row-major A): lane l -> r=l>>2, c=l&3.
// reg e0: A[r][2c..2c+1], e1: A[r+8][2c..], e2: A[r][2c+8..], e3: A[r+8][2c+8..]
__global__ void k_wmod(const float* __restrict__ weight) {
    int t = blockIdx.x * blockDim.x + threadIdx.x;
    if (t >= BATCH * 9 * 4 * 2048) return;
    int e    = t & 3;
    int lane = (t >> 2) & 31;
    int mf   = (t >> 7) & 7;
    int k16  = (t >> 10) & 1;
    int cic  = (t >> 11) & 3;
    int rest = t >> 13;
    int khkw = rest % 9;
    int b    = rest / 9;
    int r = lane >> 2, c = lane & 3;
    int co  = mf * 16 + r + (e & 1) * 8;
    int ci0 = cic * 32 + k16 * 16 + 2 * c + ((e >> 1) & 1) * 8;
    int kh = khkw / 3, kw = khkw % 3;
    float dc = g_decoef[b * COUT + co];
    float v0 = weight[((co * CIN + ci0) * 3 + kh) * 3 + kw]
               * g_s[b * CIN + ci0] * dc;
    float v1 = weight[((co * CIN + ci0 + 1) * 3 + kh) * 3 + kw]
               * g_s[b * CIN + ci0 + 1] * dc;
    g_wmod[t] = packh2(v0, v1);
}

// ---------------------------------------------------------------------------
// FP16 mma.sync implicit-GEMM conv, off-tail staging via 2x-unrolled mainloop
// with STATICALLY-NAMED double-buffered LDG registers (no dynamic reg indexing).
// CTA: (b, 128 co, 1 image row = 128 px). 256 threads = 8 warps (2m x 4n).
__global__ __launch_bounds__(256, 2)
void k_conv(const float* __restrict__ x, float* __restrict__ out) {
    extern __shared__ __align__(16) char smem_raw[];
    const uint32_t base = smem_u32(smem_raw);

    const int tid = threadIdx.x;
    const int wid = tid >> 5;
    const int lane = tid & 31;
    const int b  = blockIdx.y;
    const int y0 = blockIdx.x;
    const int mw = wid >> 2;            // 0..1
    const int nw = wid & 3;             // 0..3

    // B staging ids: thread = (px, hB); hB selects k16 block (ci 0-15 / 16-31)
    const int px = tid & 127;
    const int hB = tid >> 7;
    const int nf_s = px >> 3;
    const int laneb = (px & 7) * 4;

    float acc[4][4][4];
#pragma unroll
    for (int i = 0; i < 4; ++i)
#pragma unroll
        for (int j = 0; j < 4; ++j)
#pragma unroll
            for (int q = 0; q < 4; ++q) acc[i][j][q] = 0.f;

    float vb0[16], vb1[16];             // static double-buffered landing regs

    auto stageA = [&](int c) {
        const int s = c & 1;
        const uint32_t* asrc = g_wmod + ((size_t)b * 36 + c) * 2048;
        const uint32_t abase = base + s * A_BYTES;
#pragma unroll
        for (int it = 0; it < 2; ++it) {
            int i = tid + it * 256;        // 0..511, 16B each
            cp16(abase + i * 16, asrc + i * 4);
        }
        asm volatile("cp.async.commit_group;" ::: "memory");
    };
    auto ldgB = [&](int c, float* dst) {
        const int khkw = c >> 2, cic = c & 3;
        const int kh = khkw / 3, kw = khkw - kh * 3;
        const int gy = y0 + kh - 1;
        const int gx = px + kw - 1;
        const bool ok = ((unsigned)gy < HH) & ((unsigned)gx < WW);
        const float* p = x + (((size_t)b * CIN + cic * 32 + hB * 16) * HH + gy) * WW + gx;
#pragma unroll
        for (int j = 0; j < 16; ++j)
            dst[j] = ok ? __ldg(p + j * HW) : 0.f;
    };
    auto stsB = [&](int c, const float* v) {
        const int s = c & 1;
        const uint32_t bbase = base + B_OFF + s * B_BYTES;
        const int fb = hB * 16 + nf_s;
#pragma unroll
        for (int q = 0; q < 4; ++q) {
            uint32_t b0 = packh2(v[2 * q], v[2 * q + 1]);
            uint32_t b1 = packh2(v[2 * q + 8], v[2 * q + 9]);
            uint32_t addr = bbase + fb * B_FRAG_STRIDE + (laneb + q) * 8;
            asm volatile("st.shared.v2.b32 [%0], {%1,%2};"
                         :: "r"(addr), "r"(b0), "r"(b1) : "memory");
        }
    };
    auto mmaChunk = [&](int c) {
        const int s = c & 1;
        const uint32_t abase = base + s * A_BYTES;
        const uint32_t bbase = base + B_OFF + s * B_BYTES;
#pragma unroll
        for (int k16 = 0; k16 < 2; ++k16) {
            uint32_t av[4][4];
#pragma unroll
            for (int ai = 0; ai < 4; ++ai) {
                uint32_t addr = abase +
                    (((uint32_t)(k16 * 8 + mw * 4 + ai) * 32 + lane) << 4);
                asm volatile("ld.shared.v4.b32 {%0,%1,%2,%3}, [%4];"
                             : "=r"(av[ai][0]), "=r"(av[ai][1]),
                               "=r"(av[ai][2]), "=r"(av[ai][3])
                             : "r"(addr));
            }
            uint32_t bv[4][2];
#pragma unroll
            for (int fi = 0; fi < 4; ++fi) {
                int fb = k16 * 16 + nw * 4 + fi;
                uint32_t addr = bbase + fb * B_FRAG_STRIDE + lane * 8;
                asm volatile("ld.shared.v2.b32 {%0,%1}, [%2];"
                             : "=r"(bv[fi][0]), "=r"(bv[fi][1]) : "r"(addr));
            }
#pragma unroll
            for (int ai = 0; ai < 4; ++ai)
#pragma unroll
                for (int fi = 0; fi < 4; ++fi)
                    mma16(acc[ai][fi], av[ai], bv[fi]);
        }
    };

    // prologue: chunk 0 fully staged; chunk 1's B loads landing in vb1
    stageA(0);
    ldgB(0, vb0);
    stsB(0, vb0);
    ldgB(1, vb1);
    asm volatile("cp.async.wait_group 0;" ::: "memory");
    __syncthreads();

    for (int cc = 0; cc < NCHUNKS; cc += 2) {
        // ---- even chunk cc ----
        stageA(cc + 1);                         // cc+1 <= 35 always
        stsB(cc + 1, vb1);                      // data from ldgB 2 chunks ago
        if (cc + 2 < NCHUNKS) ldgB(cc + 2, vb0);
        mmaChunk(cc);
        asm volatile("cp.async.wait_group 0;" ::: "memory");
        __syncthreads();

        // ---- odd chunk cc+1 ----
        if (cc + 2 < NCHUNKS) {
            stageA(cc + 2);
            stsB(cc + 2, vb0);
        }
        if (cc + 3 < NCHUNKS) ldgB(cc + 3, vb1);
        mmaChunk(cc + 1);
        if (cc + 2 < NCHUNKS)
            asm volatile("cp.async.wait_group 0;" ::: "memory");
        __syncthreads();
    }

    // ---- epilogue: D fragment row r = lane>>2, cols 2q (q=lane&3) ----
    const int r = lane >> 2, q = lane & 3;
#pragma unroll
    for (int ai = 0; ai < 4; ++ai) {
        int co0 = mw * 64 + ai * 16 + r;
#pragma unroll
        for (int fi = 0; fi < 4; ++fi) {
            int pxo = nw * 32 + fi * 8 + 2 * q;
            float* o0 = out + (((size_t)b * COUT + co0) * HH + y0) * WW + pxo;
            float* o1 = o0 + 8 * (size_t)HW;       // co0 + 8
            reinterpret_cast<float2*>(o0)[0] =
                make_float2(acc[ai][fi][0], acc[ai][fi][1]);
            reinterpret_cast<float2*>(o1)[0] =
                make_float2(acc[ai][fi][2], acc[ai][fi][3]);
        }
    }
}

// ---------------------------------------------------------------------------
extern "C" void kernel_launch(void* const* d_in, const int* in_sizes, int n_in,
                              void* d_out, int out_size) {
    const float* x      = (const float*)d_in[0];
    const float* style  = (const float*)d_in[1];
    const float* weight = (const float*)d_in[2];
    const float* mod_w  = (const float*)d_in[3];
    const float* mod_b  = (const float*)d_in[4];
    float* out = (float*)d_out;

    k_modscale<<<(BATCH * CIN + 255) / 256, 256>>>(style, mod_w, mod_b);
    k_wsq<<<(COUT * CIN + 255) / 256, 256>>>(weight);
    k_decoef<<<(BATCH * COUT + 255) / 256, 256>>>();
    k_wmod<<<(BATCH * 9 * 4 * 2048 + 255) / 256, 256>>>(weight);

    cudaFuncSetAttribute(k_conv, cudaFuncAttributeMaxDynamicSharedMemorySize,
                         SMEM_TOTAL);
    dim3 grid(HH, BATCH);
    k_conv<<<grid, 256, SMEM_TOTAL>>>(x, out);
}